// round 2
// baseline (speedup 1.0000x reference)
#include <cuda_runtime.h>
#include <math.h>

#define B_  16
#define C_  256
#define H_  160
#define W_  160
#define HW_ (H_*W_)
#define NEG_SLOPE 0.001f

// ---------------- scratch (static device allocations; no cudaMalloc) -------
__device__ float g_avg[B_*HW_];
__device__ float g_max[B_*HW_];
__device__ float g_bm [B_*HW_];
__device__ float g_F  [B_*4*HW_];
__device__ float g_Cm [B_*HW_];
__device__ float g_S  [B_*H_*H_];
__device__ float g_E  [(size_t)B_*C_*HW_];   // ~419 MB

__device__ __forceinline__ float lrelu(float v) {
    return v > 0.0f ? v : NEG_SLOPE * v;
}

// ---------------- k1: channel mean/max + w_ab dot (Bm), one pass over x ----
__global__ void k1_reduce(const float* __restrict__ x,
                          const float* __restrict__ w_ab) {
    __shared__ float sw[C_];
    int tid = threadIdx.x;
    sw[tid] = w_ab[tid];            // blockDim == 256 == C_
    __syncthreads();

    int p = blockIdx.x * 256 + tid;
    int b = blockIdx.y;
    const float* xp = x + (size_t)b * C_ * HW_ + p;

    float s = 0.0f, m = -3.4e38f, d = 0.0f;
#pragma unroll 8
    for (int c = 0; c < C_; c++) {
        float v = xp[(size_t)c * HW_];
        s += v;
        m  = fmaxf(m, v);
        d  = fmaf(sw[c], v, d);
    }
    int o = b * HW_ + p;
    g_avg[o] = s * (1.0f / 256.0f);
    g_max[o] = m;
    g_bm [o] = lrelu(d);
}

// ---------------- k2: multi-scale convs on (avg,max) -> F planes + Cm ------
__global__ void k2_convs(const float* __restrict__ w1,
                         const float* __restrict__ w3,
                         const float* __restrict__ w5,
                         const float* __restrict__ w7,
                         const float* __restrict__ w_fc) {
    const int b  = blockIdx.z;
    const int h0 = blockIdx.y * 32;
    const int w0 = blockIdx.x * 32;

    __shared__ float sA[38][39];
    __shared__ float sM[38][39];

    int tid = threadIdx.y * 32 + threadIdx.x;
    const float* avgb = g_avg + b * HW_;
    const float* maxb = g_max + b * HW_;

    for (int t = tid; t < 38 * 38; t += 1024) {
        int r = t / 38, c = t - r * 38;
        int hh = h0 + r - 3, ww = w0 + c - 3;
        bool in = (hh >= 0 && hh < H_ && ww >= 0 && ww < W_);
        sA[r][c] = in ? avgb[hh * W_ + ww] : 0.0f;
        sM[r][c] = in ? maxb[hh * W_ + ww] : 0.0f;
    }
    __syncthreads();

    int ty = threadIdx.y, tx = threadIdx.x;
    int cy = ty + 3, cx = tx + 3;

    float s1 = w1[0] * sA[cy][cx] + w1[1] * sM[cy][cx];

    float s3 = 0.0f;
#pragma unroll
    for (int kh = 0; kh < 3; kh++)
#pragma unroll
        for (int kw = 0; kw < 3; kw++) {
            s3 += w3[kh * 3 + kw]      * sA[cy + kh - 1][cx + kw - 1];
            s3 += w3[9 + kh * 3 + kw]  * sM[cy + kh - 1][cx + kw - 1];
        }

    float s5 = 0.0f;
#pragma unroll
    for (int kh = 0; kh < 5; kh++)
#pragma unroll
        for (int kw = 0; kw < 5; kw++) {
            s5 += w5[kh * 5 + kw]       * sA[cy + kh - 2][cx + kw - 2];
            s5 += w5[25 + kh * 5 + kw]  * sM[cy + kh - 2][cx + kw - 2];
        }

    float s7 = 0.0f;
#pragma unroll
    for (int kh = 0; kh < 7; kh++)
#pragma unroll
        for (int kw = 0; kw < 7; kw++) {
            s7 += w7[kh * 7 + kw]       * sA[cy + kh - 3][cx + kw - 3];
            s7 += w7[49 + kh * 7 + kw]  * sM[cy + kh - 3][cx + kw - 3];
        }

    s1 = lrelu(s1); s3 = lrelu(s3); s5 = lrelu(s5); s7 = lrelu(s7);

    int h = h0 + ty, w = w0 + tx;
    size_t base = (size_t)b * 4 * HW_ + h * W_ + w;
    g_F[base]           = s1;
    g_F[base + HW_]     = s3;
    g_F[base + 2 * HW_] = s5;
    g_F[base + 3 * HW_] = s7;

    g_Cm[b * HW_ + h * W_ + w] =
        lrelu(w_fc[0] * s1 + w_fc[1] * s3 + w_fc[2] * s5 + w_fc[3] * s7);
}

// ---------------- k3: scores row h: M[h,k] = sum_w Bm[h,w]*Cm[w,k]; softmax -
__global__ void k3_attn() {
    const int h = blockIdx.x;
    const int b = blockIdx.y;
    const int tid = threadIdx.x;          // 256 threads, 160 active

    __shared__ float sb2[W_];
    __shared__ float red[256];

    const float* bmrow = g_bm + b * HW_ + h * W_;
    if (tid < W_) sb2[tid] = bmrow[tid];
    __syncthreads();

    float acc = 0.0f;
    if (tid < H_) {
        const float* cm = g_Cm + b * HW_ + tid;   // [w*W_ + k], k = tid
#pragma unroll 8
        for (int w = 0; w < W_; w++)
            acc = fmaf(sb2[w], cm[w * W_], acc);
    }

    // softmax over k
    red[tid] = (tid < H_) ? acc : -3.4e38f;
    __syncthreads();
    for (int s = 128; s > 0; s >>= 1) {
        if (tid < s) red[tid] = fmaxf(red[tid], red[tid + s]);
        __syncthreads();
    }
    float mx = red[0];
    __syncthreads();

    float e = (tid < H_) ? __expf(acc - mx) : 0.0f;
    red[tid] = e;
    __syncthreads();
    for (int s = 128; s > 0; s >>= 1) {
        if (tid < s) red[tid] += red[tid + s];
        __syncthreads();
    }
    if (tid < H_)
        g_S[((size_t)b * H_ + h) * H_ + tid] = e * (1.0f / red[0]);
}

// ---------------- k5: E_c = S_b @ D_c  (D built on the fly from F) ---------
// block = (c, b); 256 threads as 16x16, 10x10 micro-tile; K chunks of 16.
__global__ void __launch_bounds__(256, 1)
k5_E(const float* __restrict__ w_fd) {
    const int c = blockIdx.x;
    const int b = blockIdx.y;

    __shared__ float sS[16][161];   // [kk][h]
    __shared__ float sD[16][161];   // [kk][w]

    const float f0 = w_fd[c * 4 + 0];
    const float f1 = w_fd[c * 4 + 1];
    const float f2 = w_fd[c * 4 + 2];
    const float f3 = w_fd[c * 4 + 3];

    const float* Sb = g_S + (size_t)b * H_ * H_;
    const float* F0 = g_F + (size_t)b * 4 * HW_;
    const float* F1 = F0 + HW_;
    const float* F2 = F0 + 2 * HW_;
    const float* F3 = F0 + 3 * HW_;

    const int tid = threadIdx.x;
    const int ty = tid >> 4, tx = tid & 15;

    float acc[10][10];
#pragma unroll
    for (int r = 0; r < 10; r++)
#pragma unroll
        for (int s = 0; s < 10; s++) acc[r][s] = 0.0f;

    for (int kc = 0; kc < H_; kc += 16) {
        // stage S chunk: sS[kk][h] = S[h, kc+kk]  (coalesced along kk)
        for (int t = tid; t < 16 * H_; t += 256) {
            int kk = t & 15, hh = t >> 4;
            sS[kk][hh] = Sb[hh * H_ + kc + kk];
        }
        // build D chunk: sD[kk][w] = lrelu(sum_i w_fd[c,i]*F[i, kc+kk, w])
        for (int t = tid; t < 16 * W_; t += 256) {
            int kk = t / W_, ww = t - kk * W_;
            int k = kc + kk;
            float v = f0 * F0[k * W_ + ww] + f1 * F1[k * W_ + ww]
                    + f2 * F2[k * W_ + ww] + f3 * F3[k * W_ + ww];
            sD[kk][ww] = lrelu(v);
        }
        __syncthreads();

#pragma unroll
        for (int kk = 0; kk < 16; kk++) {
            float a[10], d[10];
#pragma unroll
            for (int r = 0; r < 10; r++) a[r] = sS[kk][ty + 16 * r];
#pragma unroll
            for (int s = 0; s < 10; s++) d[s] = sD[kk][tx + 16 * s];
#pragma unroll
            for (int r = 0; r < 10; r++)
#pragma unroll
                for (int s = 0; s < 10; s++)
                    acc[r][s] = fmaf(a[r], d[s], acc[r][s]);
        }
        __syncthreads();
    }

    float* Eb = g_E + ((size_t)(b * C_ + c)) * HW_;
#pragma unroll
    for (int r = 0; r < 10; r++)
#pragma unroll
        for (int s = 0; s < 10; s++)
            Eb[(ty + 16 * r) * W_ + tx + 16 * s] = acc[r][s];
}

// ---------------- k6: out = W_e @ E + x  (1x1 conv as GEMM, fused residual) -
// block tile: 128 o x 128 p, 256 threads, 8x8 micro-tile, K chunks of 16.
__global__ void __launch_bounds__(256, 1)
k6_out(const float* __restrict__ w_e,
       const float* __restrict__ x,
       float* __restrict__ out) {
    const int pb = blockIdx.x;     // 0..199
    const int ob = blockIdx.y;     // 0..1
    const int b  = blockIdx.z;

    __shared__ float sW[16][129];  // [kk][o]
    __shared__ float sE[16][128];  // [kk][p]

    const int tid = threadIdx.x;
    const int ty = tid >> 4, tx = tid & 15;
    const int o0 = ob * 128, p0 = pb * 128;

    const float* Eb = g_E + (size_t)b * C_ * HW_ + p0;

    float acc[8][8];
#pragma unroll
    for (int i = 0; i < 8; i++)
#pragma unroll
        for (int j = 0; j < 8; j++) acc[i][j] = 0.0f;

    for (int kc = 0; kc < C_; kc += 16) {
        for (int t = tid; t < 16 * 128; t += 256) {
            int kk = t & 15, oo = t >> 4;
            sW[kk][oo] = w_e[(o0 + oo) * C_ + kc + kk];
        }
        for (int t = tid; t < 16 * 128; t += 256) {
            int kk = t >> 7, pp = t & 127;
            sE[kk][pp] = Eb[(size_t)(kc + kk) * HW_ + pp];
        }
        __syncthreads();

#pragma unroll
        for (int kk = 0; kk < 16; kk++) {
            float wv[8], ev[8];
#pragma unroll
            for (int i = 0; i < 8; i++) wv[i] = sW[kk][ty + 16 * i];
#pragma unroll
            for (int j = 0; j < 8; j++) ev[j] = sE[kk][tx + 16 * j];
#pragma unroll
            for (int i = 0; i < 8; i++)
#pragma unroll
                for (int j = 0; j < 8; j++)
                    acc[i][j] = fmaf(wv[i], ev[j], acc[i][j]);
        }
        __syncthreads();
    }

    const float* xb = x   + (size_t)b * C_ * HW_ + p0;
    float*       ob_p = out + (size_t)b * C_ * HW_ + p0;
#pragma unroll
    for (int i = 0; i < 8; i++) {
        int o = o0 + ty + 16 * i;
#pragma unroll
        for (int j = 0; j < 8; j++) {
            int p = tx + 16 * j;
            ob_p[(size_t)o * HW_ + p] = acc[i][j] + xb[(size_t)o * HW_ + p];
        }
    }
}

// ---------------- launch ----------------------------------------------------
extern "C" void kernel_launch(void* const* d_in, const int* in_sizes, int n_in,
                              void* d_out, int out_size) {
    const float* x    = (const float*)d_in[0];
    const float* w1   = (const float*)d_in[1];
    const float* w3   = (const float*)d_in[2];
    const float* w5   = (const float*)d_in[3];
    const float* w7   = (const float*)d_in[4];
    const float* w_ab = (const float*)d_in[5];
    const float* w_fc = (const float*)d_in[6];
    const float* w_fd = (const float*)d_in[7];
    const float* w_e  = (const float*)d_in[8];
    float* out = (float*)d_out;

    k1_reduce<<<dim3(HW_ / 256, B_), 256>>>(x, w_ab);
    k2_convs <<<dim3(5, 5, B_), dim3(32, 32)>>>(w1, w3, w5, w7, w_fc);
    k3_attn  <<<dim3(H_, B_), 256>>>();
    k5_E     <<<dim3(C_, B_), 256>>>(w_fd);
    k6_out   <<<dim3(200, 2, B_), 256>>>(w_e, x, out);
}

// round 3
// speedup vs baseline: 1.5499x; 1.5499x over previous
#include <cuda_runtime.h>
#include <math.h>

#define B_  16
#define C_  256
#define H_  160
#define W_  160
#define HW_ (H_*W_)
#define NEG_SLOPE 0.001f

// ---------------- scratch (static device allocations; no cudaMalloc) -------
__device__ float g_avg[B_*HW_];
__device__ float g_max[B_*HW_];
__device__ float g_bm [B_*HW_];
__device__ float g_F  [B_*4*HW_];
__device__ float g_Cm [B_*HW_];
__device__ float g_S  [B_*H_*H_];
__device__ float g_E  [(size_t)B_*C_*HW_];   // ~419 MB

__device__ __forceinline__ float lrelu(float v) {
    return v > 0.0f ? v : NEG_SLOPE * v;
}

__device__ __forceinline__ float to_tf32(float v) {
    float r;
    asm("cvt.rna.tf32.f32 %0, %1;" : "=f"(r) : "f"(v));
    return r;
}

__device__ __forceinline__ void mma_tf32(float& c0, float& c1, float& c2, float& c3,
                                         float a0, float a1, float a2, float a3,
                                         float b0, float b1) {
    asm volatile(
        "mma.sync.aligned.m16n8k8.row.col.f32.tf32.tf32.f32 "
        "{%0,%1,%2,%3}, {%4,%5,%6,%7}, {%8,%9}, {%0,%1,%2,%3};"
        : "+f"(c0), "+f"(c1), "+f"(c2), "+f"(c3)
        : "r"(__float_as_uint(a0)), "r"(__float_as_uint(a1)),
          "r"(__float_as_uint(a2)), "r"(__float_as_uint(a3)),
          "r"(__float_as_uint(b0)), "r"(__float_as_uint(b1)));
}

// ---------------- k1: channel mean/max + w_ab dot (Bm), one pass over x ----
__global__ void k1_reduce(const float* __restrict__ x,
                          const float* __restrict__ w_ab) {
    __shared__ float sw[C_];
    int tid = threadIdx.x;
    sw[tid] = w_ab[tid];
    __syncthreads();

    int p = blockIdx.x * 256 + tid;
    int b = blockIdx.y;
    const float* xp = x + (size_t)b * C_ * HW_ + p;

    float s = 0.0f, m = -3.4e38f, d = 0.0f;
#pragma unroll 8
    for (int c = 0; c < C_; c++) {
        float v = xp[(size_t)c * HW_];
        s += v;
        m  = fmaxf(m, v);
        d  = fmaf(sw[c], v, d);
    }
    int o = b * HW_ + p;
    g_avg[o] = s * (1.0f / 256.0f);
    g_max[o] = m;
    g_bm [o] = lrelu(d);
}

// ---------------- k2: multi-scale convs on (avg,max) -> F planes + Cm ------
__global__ void k2_convs(const float* __restrict__ w1,
                         const float* __restrict__ w3,
                         const float* __restrict__ w5,
                         const float* __restrict__ w7,
                         const float* __restrict__ w_fc) {
    const int b  = blockIdx.z;
    const int h0 = blockIdx.y * 32;
    const int w0 = blockIdx.x * 32;

    __shared__ float sA[38][39];
    __shared__ float sM[38][39];

    int tid = threadIdx.y * 32 + threadIdx.x;
    const float* avgb = g_avg + b * HW_;
    const float* maxb = g_max + b * HW_;

    for (int t = tid; t < 38 * 38; t += 1024) {
        int r = t / 38, c = t - r * 38;
        int hh = h0 + r - 3, ww = w0 + c - 3;
        bool in = (hh >= 0 && hh < H_ && ww >= 0 && ww < W_);
        sA[r][c] = in ? avgb[hh * W_ + ww] : 0.0f;
        sM[r][c] = in ? maxb[hh * W_ + ww] : 0.0f;
    }
    __syncthreads();

    int ty = threadIdx.y, tx = threadIdx.x;
    int cy = ty + 3, cx = tx + 3;

    float s1 = w1[0] * sA[cy][cx] + w1[1] * sM[cy][cx];

    float s3 = 0.0f;
#pragma unroll
    for (int kh = 0; kh < 3; kh++)
#pragma unroll
        for (int kw = 0; kw < 3; kw++) {
            s3 += w3[kh * 3 + kw]      * sA[cy + kh - 1][cx + kw - 1];
            s3 += w3[9 + kh * 3 + kw]  * sM[cy + kh - 1][cx + kw - 1];
        }

    float s5 = 0.0f;
#pragma unroll
    for (int kh = 0; kh < 5; kh++)
#pragma unroll
        for (int kw = 0; kw < 5; kw++) {
            s5 += w5[kh * 5 + kw]       * sA[cy + kh - 2][cx + kw - 2];
            s5 += w5[25 + kh * 5 + kw]  * sM[cy + kh - 2][cx + kw - 2];
        }

    float s7 = 0.0f;
#pragma unroll
    for (int kh = 0; kh < 7; kh++)
#pragma unroll
        for (int kw = 0; kw < 7; kw++) {
            s7 += w7[kh * 7 + kw]       * sA[cy + kh - 3][cx + kw - 3];
            s7 += w7[49 + kh * 7 + kw]  * sM[cy + kh - 3][cx + kw - 3];
        }

    s1 = lrelu(s1); s3 = lrelu(s3); s5 = lrelu(s5); s7 = lrelu(s7);

    int h = h0 + ty, w = w0 + tx;
    size_t base = (size_t)b * 4 * HW_ + h * W_ + w;
    g_F[base]           = s1;
    g_F[base + HW_]     = s3;
    g_F[base + 2 * HW_] = s5;
    g_F[base + 3 * HW_] = s7;

    g_Cm[b * HW_ + h * W_ + w] =
        lrelu(w_fc[0] * s1 + w_fc[1] * s3 + w_fc[2] * s5 + w_fc[3] * s7);
}

// ---------------- k3: scores row h + softmax (exact fp32) ------------------
__global__ void k3_attn() {
    const int h = blockIdx.x;
    const int b = blockIdx.y;
    const int tid = threadIdx.x;

    __shared__ float sb2[W_];
    __shared__ float red[256];

    const float* bmrow = g_bm + b * HW_ + h * W_;
    if (tid < W_) sb2[tid] = bmrow[tid];
    __syncthreads();

    float acc = 0.0f;
    if (tid < H_) {
        const float* cm = g_Cm + b * HW_ + tid;
#pragma unroll 8
        for (int w = 0; w < W_; w++)
            acc = fmaf(sb2[w], cm[w * W_], acc);
    }

    red[tid] = (tid < H_) ? acc : -3.4e38f;
    __syncthreads();
    for (int s = 128; s > 0; s >>= 1) {
        if (tid < s) red[tid] = fmaxf(red[tid], red[tid + s]);
        __syncthreads();
    }
    float mx = red[0];
    __syncthreads();

    float e = (tid < H_) ? __expf(acc - mx) : 0.0f;
    red[tid] = e;
    __syncthreads();
    for (int s = 128; s > 0; s >>= 1) {
        if (tid < s) red[tid] += red[tid + s];
        __syncthreads();
    }
    if (tid < H_)
        g_S[((size_t)b * H_ + h) * H_ + tid] = e * (1.0f / red[0]);
}

// ---------------- k5: E_c = S_b @ D_c via TF32 MMA -------------------------
// block = (c, b); 256 threads = 8 warps in 2x4; warp tile 80x40; K chunks 32.
#define PA5 36     // sA pitch  (m-major [160][36]) : 36%32=4 -> conflict-free
#define PB5 168    // sB pitch  (k-major [32][168]) : 168%32=8 -> conflict-free
__global__ void __launch_bounds__(256, 1)
k5_E(const float* __restrict__ w_fd) {
    const int c = blockIdx.x;
    const int b = blockIdx.y;

    __shared__ float sA[H_ * PA5];   // S chunk [m][k], tf32-rounded
    __shared__ float sB[32 * PB5];   // D chunk [k][n], tf32-rounded

    const float f0 = w_fd[c * 4 + 0];
    const float f1 = w_fd[c * 4 + 1];
    const float f2 = w_fd[c * 4 + 2];
    const float f3 = w_fd[c * 4 + 3];

    const float* Sb = g_S + (size_t)b * H_ * H_;
    const float* F0 = g_F + (size_t)b * 4 * HW_;
    const float* F1 = F0 + HW_;
    const float* F2 = F0 + 2 * HW_;
    const float* F3 = F0 + 3 * HW_;

    const int tid  = threadIdx.x;
    const int wid  = tid >> 5;
    const int lane = tid & 31;
    const int qr   = lane >> 2;    // 0..7
    const int qc   = lane & 3;     // 0..3
    const int mw0  = (wid & 1) * 80;   // warp M offset
    const int nw0  = (wid >> 1) * 40;  // warp N offset

    float acc[5][5][4];
#pragma unroll
    for (int i = 0; i < 5; i++)
#pragma unroll
        for (int j = 0; j < 5; j++)
#pragma unroll
            for (int q = 0; q < 4; q++) acc[i][j][q] = 0.0f;

    for (int kc = 0; kc < H_; kc += 32) {
        // stage S: sA[m][k] = S[m][kc+k]
        for (int t = tid; t < H_ * 32; t += 256) {
            int k = t & 31, m = t >> 5;
            sA[m * PA5 + k] = to_tf32(Sb[m * H_ + kc + k]);
        }
        // stage D: sB[k][w] = lrelu(sum_i f_i * F_i[kc+k][w])
        for (int t = tid; t < 32 * W_; t += 256) {
            int w = t % W_, k = t / W_;
            int row = (kc + k) * W_;
            float v = f0 * F0[row + w] + f1 * F1[row + w]
                    + f2 * F2[row + w] + f3 * F3[row + w];
            sB[k * PB5 + w] = to_tf32(lrelu(v));
        }
        __syncthreads();

#pragma unroll
        for (int kk = 0; kk < 32; kk += 8) {
            float Af[5][4];
#pragma unroll
            for (int mi = 0; mi < 5; mi++) {
                int m0 = mw0 + mi * 16;
                Af[mi][0] = sA[(m0 + qr)     * PA5 + kk + qc];
                Af[mi][1] = sA[(m0 + qr + 8) * PA5 + kk + qc];
                Af[mi][2] = sA[(m0 + qr)     * PA5 + kk + qc + 4];
                Af[mi][3] = sA[(m0 + qr + 8) * PA5 + kk + qc + 4];
            }
#pragma unroll
            for (int ni = 0; ni < 5; ni++) {
                int n0 = nw0 + ni * 8;
                float b0 = sB[(kk + qc)     * PB5 + n0 + qr];
                float b1 = sB[(kk + qc + 4) * PB5 + n0 + qr];
#pragma unroll
                for (int mi = 0; mi < 5; mi++)
                    mma_tf32(acc[mi][ni][0], acc[mi][ni][1],
                             acc[mi][ni][2], acc[mi][ni][3],
                             Af[mi][0], Af[mi][1], Af[mi][2], Af[mi][3],
                             b0, b1);
            }
        }
        __syncthreads();
    }

    float* Eb = g_E + ((size_t)(b * C_ + c)) * HW_;
#pragma unroll
    for (int mi = 0; mi < 5; mi++) {
        int r0 = mw0 + mi * 16 + qr;
#pragma unroll
        for (int ni = 0; ni < 5; ni++) {
            int col = nw0 + ni * 8 + 2 * qc;
            *(float2*)&Eb[r0 * W_ + col]       = make_float2(acc[mi][ni][0], acc[mi][ni][1]);
            *(float2*)&Eb[(r0 + 8) * W_ + col] = make_float2(acc[mi][ni][2], acc[mi][ni][3]);
        }
    }
}

// ---------------- k6: out = W_e @ E + x via TF32 MMA -----------------------
// tile 128(o) x 128(p), 256 threads = 8 warps 2x4; warp tile 64x32; K chunk 32.
#define PA6 36     // sW pitch [128][36]
#define PB6 136    // sE pitch [32][136] : 136%32=8
__global__ void __launch_bounds__(256, 1)
k6_out(const float* __restrict__ w_e,
       const float* __restrict__ x,
       float* __restrict__ out) {
    const int pb = blockIdx.x;     // 0..199
    const int ob = blockIdx.y;     // 0..1
    const int b  = blockIdx.z;

    __shared__ float sW[128 * PA6];
    __shared__ float sE[32 * PB6];

    const int tid  = threadIdx.x;
    const int wid  = tid >> 5;
    const int lane = tid & 31;
    const int qr   = lane >> 2;
    const int qc   = lane & 3;
    const int mw0  = (wid & 1) * 64;
    const int nw0  = (wid >> 1) * 32;
    const int o0 = ob * 128, p0 = pb * 128;

    const float* Eb = g_E + (size_t)b * C_ * HW_ + p0;

    float acc[4][4][4];
#pragma unroll
    for (int i = 0; i < 4; i++)
#pragma unroll
        for (int j = 0; j < 4; j++)
#pragma unroll
            for (int q = 0; q < 4; q++) acc[i][j][q] = 0.0f;

    for (int kc = 0; kc < C_; kc += 32) {
        for (int t = tid; t < 128 * 32; t += 256) {
            int k = t & 31, m = t >> 5;
            sW[m * PA6 + k] = to_tf32(w_e[(o0 + m) * C_ + kc + k]);
        }
        for (int t = tid; t < 32 * 128; t += 256) {
            int p = t & 127, k = t >> 7;
            sE[k * PB6 + p] = to_tf32(Eb[(size_t)(kc + k) * HW_ + p]);
        }
        __syncthreads();

#pragma unroll
        for (int kk = 0; kk < 32; kk += 8) {
            float Af[4][4];
#pragma unroll
            for (int mi = 0; mi < 4; mi++) {
                int m0 = mw0 + mi * 16;
                Af[mi][0] = sW[(m0 + qr)     * PA6 + kk + qc];
                Af[mi][1] = sW[(m0 + qr + 8) * PA6 + kk + qc];
                Af[mi][2] = sW[(m0 + qr)     * PA6 + kk + qc + 4];
                Af[mi][3] = sW[(m0 + qr + 8) * PA6 + kk + qc + 4];
            }
#pragma unroll
            for (int ni = 0; ni < 4; ni++) {
                int n0 = nw0 + ni * 8;
                float b0 = sE[(kk + qc)     * PB6 + n0 + qr];
                float b1 = sE[(kk + qc + 4) * PB6 + n0 + qr];
#pragma unroll
                for (int mi = 0; mi < 4; mi++)
                    mma_tf32(acc[mi][ni][0], acc[mi][ni][1],
                             acc[mi][ni][2], acc[mi][ni][3],
                             Af[mi][0], Af[mi][1], Af[mi][2], Af[mi][3],
                             b0, b1);
            }
        }
        __syncthreads();
    }

    const float* xb  = x   + (size_t)b * C_ * HW_ + p0;
    float*       obp = out + (size_t)b * C_ * HW_ + p0;
#pragma unroll
    for (int mi = 0; mi < 4; mi++) {
        int o = o0 + mw0 + mi * 16 + qr;
#pragma unroll
        for (int ni = 0; ni < 4; ni++) {
            int col = nw0 + ni * 8 + 2 * qc;
            {
                float2 xv = *(const float2*)&xb[(size_t)o * HW_ + col];
                *(float2*)&obp[(size_t)o * HW_ + col] =
                    make_float2(acc[mi][ni][0] + xv.x, acc[mi][ni][1] + xv.y);
            }
            {
                float2 xv = *(const float2*)&xb[(size_t)(o + 8) * HW_ + col];
                *(float2*)&obp[(size_t)(o + 8) * HW_ + col] =
                    make_float2(acc[mi][ni][2] + xv.x, acc[mi][ni][3] + xv.y);
            }
        }
    }
}

// ---------------- launch ----------------------------------------------------
extern "C" void kernel_launch(void* const* d_in, const int* in_sizes, int n_in,
                              void* d_out, int out_size) {
    const float* x    = (const float*)d_in[0];
    const float* w1   = (const float*)d_in[1];
    const float* w3   = (const float*)d_in[2];
    const float* w5   = (const float*)d_in[3];
    const float* w7   = (const float*)d_in[4];
    const float* w_ab = (const float*)d_in[5];
    const float* w_fc = (const float*)d_in[6];
    const float* w_fd = (const float*)d_in[7];
    const float* w_e  = (const float*)d_in[8];
    float* out = (float*)d_out;

    k1_reduce<<<dim3(HW_ / 256, B_), 256>>>(x, w_ab);
    k2_convs <<<dim3(5, 5, B_), dim3(32, 32)>>>(w1, w3, w5, w7, w_fc);
    k3_attn  <<<dim3(H_, B_), 256>>>();
    k5_E     <<<dim3(C_, B_), 256>>>(w_fd);
    k6_out   <<<dim3(200, 2, B_), 256>>>(w_e, x, out);
}

// round 8
// speedup vs baseline: 2.9793x; 1.9223x over previous
#include <cuda_runtime.h>
#include <cstdint>
#include <math.h>

#define B_  16
#define C_  256
#define H_  160
#define W_  160
#define HW_ (H_*W_)
#define NEG_SLOPE 0.001f

// ---------------- scratch -----------------------------------------------
__device__ float g_avg[B_*HW_];
__device__ float g_max[B_*HW_];
__device__ float g_bm [B_*HW_];
__device__ float g_F  [B_*4*HW_];
__device__ float g_Cm [B_*HW_];
__device__ float g_S  [B_*H_*H_];
__device__ float g_E  [(size_t)B_*C_*HW_];   // ~419 MB

__device__ __forceinline__ float lrelu(float v) {
    return v > 0.0f ? v : NEG_SLOPE * v;
}

__device__ __forceinline__ void cp_async16(void* smem_dst, const void* gmem_src) {
    unsigned int s = (unsigned int)__cvta_generic_to_shared(smem_dst);
    asm volatile("cp.async.ca.shared.global [%0], [%1], 16;\n" :: "r"(s), "l"(gmem_src));
}
__device__ __forceinline__ void cp_commit() {
    asm volatile("cp.async.commit_group;\n");
}
__device__ __forceinline__ void cp_wait_all() {
    asm volatile("cp.async.wait_group 0;\n");
}

// fp32 bits fed directly as tf32 operands (HW truncates low mantissa bits)
__device__ __forceinline__ void mma_tf32(float& c0, float& c1, float& c2, float& c3,
                                         float a0, float a1, float a2, float a3,
                                         float b0, float b1) {
    asm volatile(
        "mma.sync.aligned.m16n8k8.row.col.f32.tf32.tf32.f32 "
        "{%0,%1,%2,%3}, {%4,%5,%6,%7}, {%8,%9}, {%0,%1,%2,%3};"
        : "+f"(c0), "+f"(c1), "+f"(c2), "+f"(c3)
        : "r"(__float_as_uint(a0)), "r"(__float_as_uint(a1)),
          "r"(__float_as_uint(a2)), "r"(__float_as_uint(a3)),
          "r"(__float_as_uint(b0)), "r"(__float_as_uint(b1)));
}

// ---------------- k1: channel mean/max + w_ab dot, float4 ----------------
__global__ void k1_reduce(const float* __restrict__ x,
                          const float* __restrict__ w_ab) {
    __shared__ float sw[C_];
    int tid = threadIdx.x;
    sw[tid] = w_ab[tid];
    __syncthreads();

    int p4 = blockIdx.x * 256 + tid;          // float4 index
    int b  = blockIdx.y;
    const float4* xp = (const float4*)(x + (size_t)b * C_ * HW_) + p4;

    float4 s = make_float4(0,0,0,0);
    float4 m = make_float4(-3.4e38f,-3.4e38f,-3.4e38f,-3.4e38f);
    float4 d = make_float4(0,0,0,0);
#pragma unroll 4
    for (int c = 0; c < C_; c++) {
        float4 v = xp[(size_t)c * (HW_/4)];
        float wc = sw[c];
        s.x += v.x; s.y += v.y; s.z += v.z; s.w += v.w;
        m.x = fmaxf(m.x, v.x); m.y = fmaxf(m.y, v.y);
        m.z = fmaxf(m.z, v.z); m.w = fmaxf(m.w, v.w);
        d.x = fmaf(wc, v.x, d.x); d.y = fmaf(wc, v.y, d.y);
        d.z = fmaf(wc, v.z, d.z); d.w = fmaf(wc, v.w, d.w);
    }
    int o = b * (HW_/4) + p4;
    const float inv = 1.0f / 256.0f;
    ((float4*)g_avg)[o] = make_float4(s.x*inv, s.y*inv, s.z*inv, s.w*inv);
    ((float4*)g_max)[o] = m;
    ((float4*)g_bm )[o] = make_float4(lrelu(d.x), lrelu(d.y), lrelu(d.z), lrelu(d.w));
}

// ---------------- k2: multi-scale convs -> F planes + Cm -----------------
__global__ void k2_convs(const float* __restrict__ w1,
                         const float* __restrict__ w3,
                         const float* __restrict__ w5,
                         const float* __restrict__ w7,
                         const float* __restrict__ w_fc) {
    const int b  = blockIdx.z;
    const int h0 = blockIdx.y * 32;
    const int w0 = blockIdx.x * 32;

    __shared__ float sA[38][39];
    __shared__ float sM[38][39];

    int tid = threadIdx.y * 32 + threadIdx.x;
    const float* avgb = g_avg + b * HW_;
    const float* maxb = g_max + b * HW_;

    for (int t = tid; t < 38 * 38; t += 1024) {
        int r = t / 38, c = t - r * 38;
        int hh = h0 + r - 3, ww = w0 + c - 3;
        bool in = (hh >= 0 && hh < H_ && ww >= 0 && ww < W_);
        sA[r][c] = in ? avgb[hh * W_ + ww] : 0.0f;
        sM[r][c] = in ? maxb[hh * W_ + ww] : 0.0f;
    }
    __syncthreads();

    int ty = threadIdx.y, tx = threadIdx.x;
    int cy = ty + 3, cx = tx + 3;

    float s1 = w1[0] * sA[cy][cx] + w1[1] * sM[cy][cx];

    float s3 = 0.0f;
#pragma unroll
    for (int kh = 0; kh < 3; kh++)
#pragma unroll
        for (int kw = 0; kw < 3; kw++) {
            s3 += w3[kh * 3 + kw]      * sA[cy + kh - 1][cx + kw - 1];
            s3 += w3[9 + kh * 3 + kw]  * sM[cy + kh - 1][cx + kw - 1];
        }

    float s5 = 0.0f;
#pragma unroll
    for (int kh = 0; kh < 5; kh++)
#pragma unroll
        for (int kw = 0; kw < 5; kw++) {
            s5 += w5[kh * 5 + kw]       * sA[cy + kh - 2][cx + kw - 2];
            s5 += w5[25 + kh * 5 + kw]  * sM[cy + kh - 2][cx + kw - 2];
        }

    float s7 = 0.0f;
#pragma unroll
    for (int kh = 0; kh < 7; kh++)
#pragma unroll
        for (int kw = 0; kw < 7; kw++) {
            s7 += w7[kh * 7 + kw]       * sA[cy + kh - 3][cx + kw - 3];
            s7 += w7[49 + kh * 7 + kw]  * sM[cy + kh - 3][cx + kw - 3];
        }

    s1 = lrelu(s1); s3 = lrelu(s3); s5 = lrelu(s5); s7 = lrelu(s7);

    int h = h0 + ty, w = w0 + tx;
    size_t base = (size_t)b * 4 * HW_ + h * W_ + w;
    g_F[base]           = s1;
    g_F[base + HW_]     = s3;
    g_F[base + 2 * HW_] = s5;
    g_F[base + 3 * HW_] = s7;

    g_Cm[b * HW_ + h * W_ + w] =
        lrelu(w_fc[0] * s1 + w_fc[1] * s3 + w_fc[2] * s5 + w_fc[3] * s7);
}

// ---------------- k3: attention scores + softmax (exact fp32) ------------
__global__ void k3_attn() {
    const int h = blockIdx.x;
    const int b = blockIdx.y;
    const int tid = threadIdx.x;

    __shared__ float sb2[W_];
    __shared__ float red[256];

    const float* bmrow = g_bm + b * HW_ + h * W_;
    if (tid < W_) sb2[tid] = bmrow[tid];
    __syncthreads();

    float acc = 0.0f;
    if (tid < H_) {
        const float* cm = g_Cm + b * HW_ + tid;
#pragma unroll 8
        for (int w = 0; w < W_; w++)
            acc = fmaf(sb2[w], cm[w * W_], acc);
    }

    red[tid] = (tid < H_) ? acc : -3.4e38f;
    __syncthreads();
    for (int s = 128; s > 0; s >>= 1) {
        if (tid < s) red[tid] = fmaxf(red[tid], red[tid + s]);
        __syncthreads();
    }
    float mx = red[0];
    __syncthreads();

    float e = (tid < H_) ? __expf(acc - mx) : 0.0f;
    red[tid] = e;
    __syncthreads();
    for (int s = 128; s > 0; s >>= 1) {
        if (tid < s) red[tid] += red[tid + s];
        __syncthreads();
    }
    if (tid < H_)
        g_S[((size_t)b * H_ + h) * H_ + tid] = e * (1.0f / red[0]);
}

// ---------------- k5: E_c = S_b @ D_c, TF32 MMA, S resident in smem -------
// block=(c,b); 8 warps 2x4; warp tile 80x40; K chunk 16, D double-buffered.
#define SA_P 164           // S pitch: 164%32=4 -> conflict-free fragments
#define SB_P 168           // D pitch: 168%32=8 -> conflict-free fragments
#define K5_SMEM ((H_*SA_P + 2*16*SB_P)*4)
__global__ void __launch_bounds__(256)
k5_E(const float* __restrict__ w_fd) {
    extern __shared__ float sm5[];
    float* sA = sm5;                   // [160][SA_P] : full S tile
    float* sB = sm5 + H_ * SA_P;       // [2][16][SB_P]

    const int c = blockIdx.x;
    const int b = blockIdx.y;

    const float f0 = w_fd[c * 4 + 0];
    const float f1 = w_fd[c * 4 + 1];
    const float f2 = w_fd[c * 4 + 2];
    const float f3 = w_fd[c * 4 + 3];

    const float* Sb = g_S + (size_t)b * H_ * H_;
    const float* F0 = g_F + (size_t)b * 4 * HW_;
    const float* F1 = F0 + HW_;
    const float* F2 = F0 + 2 * HW_;
    const float* F3 = F0 + 3 * HW_;

    const int tid  = threadIdx.x;
    const int wid  = tid >> 5;
    const int lane = tid & 31;
    const int qr   = lane >> 2;
    const int qc   = lane & 3;
    const int mw0  = (wid & 1) * 80;
    const int nw0  = (wid >> 1) * 40;

    // stage full S via cp.async: 160 rows x 40 16B units
    for (int t = tid; t < H_ * 40; t += 256) {
        int row = t / 40, seg = t - row * 40;
        cp_async16(sA + row * SA_P + seg * 4, Sb + row * H_ + seg * 4);
    }
    cp_commit();

    // compute first D chunk (kc=0) into buffer 0 (float2 granularity)
    {
        float* dst = sB;
        for (int j = 0; j < 5; j++) {
            int i2 = tid + j * 256;            // 1280 float2 per chunk
            int k  = i2 / 80, w2 = (i2 - k * 80) * 2;
            int row = k * W_ + w2;
            float2 a0 = *(const float2*)&F0[row];
            float2 a1 = *(const float2*)&F1[row];
            float2 a2 = *(const float2*)&F2[row];
            float2 a3 = *(const float2*)&F3[row];
            float2 r;
            r.x = lrelu(f0*a0.x + f1*a1.x + f2*a2.x + f3*a3.x);
            r.y = lrelu(f0*a0.y + f1*a1.y + f2*a2.y + f3*a3.y);
            *(float2*)&dst[k * SB_P + w2] = r;
        }
    }
    cp_wait_all();
    __syncthreads();

    float acc[5][5][4];
#pragma unroll
    for (int i = 0; i < 5; i++)
#pragma unroll
        for (int j = 0; j < 5; j++)
#pragma unroll
            for (int q = 0; q < 4; q++) acc[i][j][q] = 0.0f;

    int buf = 0;
    for (int it = 0; it < 10; it++) {
        const int kc = it * 16;
        const float* bcur = sB + buf * 16 * SB_P;

#pragma unroll
        for (int kk = 0; kk < 16; kk += 8) {
            float Af[5][4];
#pragma unroll
            for (int mi = 0; mi < 5; mi++) {
                int m0 = mw0 + mi * 16;
                const float* ar = sA + kc + kk + qc;
                Af[mi][0] = ar[(m0 + qr)     * SA_P];
                Af[mi][1] = ar[(m0 + qr + 8) * SA_P];
                Af[mi][2] = ar[(m0 + qr)     * SA_P + 4];
                Af[mi][3] = ar[(m0 + qr + 8) * SA_P + 4];
            }
#pragma unroll
            for (int ni = 0; ni < 5; ni++) {
                int n0 = nw0 + ni * 8;
                float b0 = bcur[(kk + qc)     * SB_P + n0 + qr];
                float b1 = bcur[(kk + qc + 4) * SB_P + n0 + qr];
#pragma unroll
                for (int mi = 0; mi < 5; mi++)
                    mma_tf32(acc[mi][ni][0], acc[mi][ni][1],
                             acc[mi][ni][2], acc[mi][ni][3],
                             Af[mi][0], Af[mi][1], Af[mi][2], Af[mi][3],
                             b0, b1);
            }
        }

        if (it < 9) {                         // build next D chunk
            float* dst = sB + (buf ^ 1) * 16 * SB_P;
            const int kn = kc + 16;
#pragma unroll
            for (int j = 0; j < 5; j++) {
                int i2 = tid + j * 256;
                int k  = i2 / 80, w2 = (i2 - k * 80) * 2;
                int row = (kn + k) * W_ + w2;
                float2 a0 = *(const float2*)&F0[row];
                float2 a1 = *(const float2*)&F1[row];
                float2 a2 = *(const float2*)&F2[row];
                float2 a3 = *(const float2*)&F3[row];
                float2 r;
                r.x = lrelu(f0*a0.x + f1*a1.x + f2*a2.x + f3*a3.x);
                r.y = lrelu(f0*a0.y + f1*a1.y + f2*a2.y + f3*a3.y);
                *(float2*)&dst[k * SB_P + w2] = r;
            }
        }
        __syncthreads();
        buf ^= 1;
    }

    float* Eb = g_E + ((size_t)(b * C_ + c)) * HW_;
#pragma unroll
    for (int mi = 0; mi < 5; mi++) {
        int r0 = mw0 + mi * 16 + qr;
#pragma unroll
        for (int ni = 0; ni < 5; ni++) {
            int col = nw0 + ni * 8 + 2 * qc;
            *(float2*)&Eb[r0 * W_ + col]       = make_float2(acc[mi][ni][0], acc[mi][ni][1]);
            *(float2*)&Eb[(r0 + 8) * W_ + col] = make_float2(acc[mi][ni][2], acc[mi][ni][3]);
        }
    }
}

// ---------------- k6: out = W_e @ E + x, TF32 MMA, W resident in smem -----
// tile 128(o) x 128(p); 8 warps 2x4; warp 64x32; K chunk 16, E double-buffered.
#define SW_P 260           // 260%32=4 -> conflict-free
#define SE_P 136           // 136%32=8 -> conflict-free
#define K6_SMEM ((128*SW_P + 2*16*SE_P)*4)
__global__ void __launch_bounds__(256)
k6_out(const float* __restrict__ w_e,
       const float* __restrict__ x,
       float* __restrict__ out) {
    extern __shared__ float sm6[];
    float* sW = sm6;                   // [128][SW_P] : full W_e tile (all K)
    float* sE = sm6 + 128 * SW_P;      // [2][16][SE_P]

    const int pb = blockIdx.x;     // 0..199
    const int ob = blockIdx.y;     // 0..1
    const int b  = blockIdx.z;

    const int tid  = threadIdx.x;
    const int wid  = tid >> 5;
    const int lane = tid & 31;
    const int qr   = lane >> 2;
    const int qc   = lane & 3;
    const int mw0  = (wid & 1) * 64;
    const int nw0  = (wid >> 1) * 32;
    const int o0 = ob * 128, p0 = pb * 128;

    const float* Eb = g_E + (size_t)b * C_ * HW_ + p0;

    // stage full W tile: 128 rows x 64 16B units
    for (int t = tid; t < 128 * 64; t += 256) {
        int row = t >> 6, seg = t & 63;
        cp_async16(sW + row * SW_P + seg * 4, w_e + (o0 + row) * C_ + seg * 4);
    }
    // stage first E chunk: 16 rows x 32 units
    for (int t = tid; t < 512; t += 256) {
        int row = t >> 5, seg = t & 31;
        cp_async16(sE + row * SE_P + seg * 4, Eb + (size_t)row * HW_ + seg * 4);
    }
    cp_commit();
    cp_wait_all();
    __syncthreads();

    float acc[4][4][4];
#pragma unroll
    for (int i = 0; i < 4; i++)
#pragma unroll
        for (int j = 0; j < 4; j++)
#pragma unroll
            for (int q = 0; q < 4; q++) acc[i][j][q] = 0.0f;

    int buf = 0;
    for (int it = 0; it < 16; it++) {
        const int kc = it * 16;
        if (it < 15) {                    // prefetch next E chunk
            float* dst = sE + (buf ^ 1) * 16 * SE_P;
            for (int t = tid; t < 512; t += 256) {
                int row = t >> 5, seg = t & 31;
                cp_async16(dst + row * SE_P + seg * 4,
                           Eb + (size_t)(kc + 16 + row) * HW_ + seg * 4);
            }
            cp_commit();
        }

        const float* ecur = sE + buf * 16 * SE_P;
#pragma unroll
        for (int kk = 0; kk < 16; kk += 8) {
            float Af[4][4];
#pragma unroll
            for (int mi = 0; mi < 4; mi++) {
                int m0 = mw0 + mi * 16;
                const float* ar = sW + kc + kk + qc;
                Af[mi][0] = ar[(m0 + qr)     * SW_P];
                Af[mi][1] = ar[(m0 + qr + 8) * SW_P];
                Af[mi][2] = ar[(m0 + qr)     * SW_P + 4];
                Af[mi][3] = ar[(m0 + qr + 8) * SW_P + 4];
            }
#pragma unroll
            for (int ni = 0; ni < 4; ni++) {
                int n0 = nw0 + ni * 8;
                float b0 = ecur[(kk + qc)     * SE_P + n0 + qr];
                float b1 = ecur[(kk + qc + 4) * SE_P + n0 + qr];
#pragma unroll
                for (int mi = 0; mi < 4; mi++)
                    mma_tf32(acc[mi][ni][0], acc[mi][ni][1],
                             acc[mi][ni][2], acc[mi][ni][3],
                             Af[mi][0], Af[mi][1], Af[mi][2], Af[mi][3],
                             b0, b1);
            }
        }

        if (it < 15) cp_wait_all();
        __syncthreads();
        buf ^= 1;
    }

    const float* xb  = x   + (size_t)b * C_ * HW_ + p0;
    float*       obp = out + (size_t)b * C_ * HW_ + p0;
#pragma unroll
    for (int mi = 0; mi < 4; mi++) {
        int o = o0 + mw0 + mi * 16 + qr;
#pragma unroll
        for (int ni = 0; ni < 4; ni++) {
            int col = nw0 + ni * 8 + 2 * qc;
            {
                float2 xv = *(const float2*)&xb[(size_t)o * HW_ + col];
                *(float2*)&obp[(size_t)o * HW_ + col] =
                    make_float2(acc[mi][ni][0] + xv.x, acc[mi][ni][1] + xv.y);
            }
            {
                float2 xv = *(const float2*)&xb[(size_t)(o + 8) * HW_ + col];
                *(float2*)&obp[(size_t)(o + 8) * HW_ + col] =
                    make_float2(acc[mi][ni][2] + xv.x, acc[mi][ni][3] + xv.y);
            }
        }
    }
}

// ---------------- launch --------------------------------------------------
extern "C" void kernel_launch(void* const* d_in, const int* in_sizes, int n_in,
                              void* d_out, int out_size) {
    const float* x    = (const float*)d_in[0];
    const float* w1   = (const float*)d_in[1];
    const float* w3   = (const float*)d_in[2];
    const float* w5   = (const float*)d_in[3];
    const float* w7   = (const float*)d_in[4];
    const float* w_ab = (const float*)d_in[5];
    const float* w_fc = (const float*)d_in[6];
    const float* w_fd = (const float*)d_in[7];
    const float* w_e  = (const float*)d_in[8];
    float* out = (float*)d_out;

    cudaFuncSetAttribute(k5_E,  cudaFuncAttributeMaxDynamicSharedMemorySize, K5_SMEM);
    cudaFuncSetAttribute(k6_out, cudaFuncAttributeMaxDynamicSharedMemorySize, K6_SMEM);

    k1_reduce<<<dim3(HW_ / 1024, B_), 256>>>(x, w_ab);
    k2_convs <<<dim3(5, 5, B_), dim3(32, 32)>>>(w1, w3, w5, w7, w_fc);
    k3_attn  <<<dim3(H_, B_), 256>>>();
    k5_E     <<<dim3(C_, B_), 256, K5_SMEM>>>(w_fd);
    k6_out   <<<dim3(200, 2, B_), 256, K6_SMEM>>>(w_e, x, out);
}

// round 10
// speedup vs baseline: 3.4540x; 1.1593x over previous
#include <cuda_runtime.h>
#include <cstdint>
#include <math.h>

#define B_  16
#define C_  256
#define H_  160
#define W_  160
#define HW_ (H_*W_)
#define NEG_SLOPE 0.001f

// ---------------- scratch -----------------------------------------------
__device__ float g_avg[B_*HW_];
__device__ float g_max[B_*HW_];
__device__ float g_bm [B_*HW_];
__device__ float g_F  [B_*4*HW_];
__device__ float g_Cm [B_*HW_];
__device__ float g_S  [B_*H_*H_];
__device__ float g_E  [(size_t)B_*C_*HW_];   // ~419 MB

__device__ __forceinline__ float lrelu(float v) {
    return v > 0.0f ? v : NEG_SLOPE * v;
}

__device__ __forceinline__ void cp_async16(void* smem_dst, const void* gmem_src) {
    unsigned int s = (unsigned int)__cvta_generic_to_shared(smem_dst);
    asm volatile("cp.async.ca.shared.global [%0], [%1], 16;\n" :: "r"(s), "l"(gmem_src));
}
__device__ __forceinline__ void cp_commit() {
    asm volatile("cp.async.commit_group;\n");
}
template<int N>
__device__ __forceinline__ void cp_wait() {
    asm volatile("cp.async.wait_group %0;\n" :: "n"(N));
}

// fp32 bits fed directly as tf32 operands (HW truncates low mantissa bits)
__device__ __forceinline__ void mma_tf32(float& c0, float& c1, float& c2, float& c3,
                                         float a0, float a1, float a2, float a3,
                                         float b0, float b1) {
    asm volatile(
        "mma.sync.aligned.m16n8k8.row.col.f32.tf32.tf32.f32 "
        "{%0,%1,%2,%3}, {%4,%5,%6,%7}, {%8,%9}, {%0,%1,%2,%3};"
        : "+f"(c0), "+f"(c1), "+f"(c2), "+f"(c3)
        : "r"(__float_as_uint(a0)), "r"(__float_as_uint(a1)),
          "r"(__float_as_uint(a2)), "r"(__float_as_uint(a3)),
          "r"(__float_as_uint(b0)), "r"(__float_as_uint(b1)));
}

// ---------------- k1: channel mean/max + w_ab dot, float4 ----------------
__global__ void k1_reduce(const float* __restrict__ x,
                          const float* __restrict__ w_ab) {
    __shared__ float sw[C_];
    int tid = threadIdx.x;
    sw[tid] = w_ab[tid];
    __syncthreads();

    int p4 = blockIdx.x * 256 + tid;
    int b  = blockIdx.y;
    const float4* xp = (const float4*)(x + (size_t)b * C_ * HW_) + p4;

    float4 s = make_float4(0,0,0,0);
    float4 m = make_float4(-3.4e38f,-3.4e38f,-3.4e38f,-3.4e38f);
    float4 d = make_float4(0,0,0,0);
#pragma unroll 4
    for (int c = 0; c < C_; c++) {
        float4 v = xp[(size_t)c * (HW_/4)];
        float wc = sw[c];
        s.x += v.x; s.y += v.y; s.z += v.z; s.w += v.w;
        m.x = fmaxf(m.x, v.x); m.y = fmaxf(m.y, v.y);
        m.z = fmaxf(m.z, v.z); m.w = fmaxf(m.w, v.w);
        d.x = fmaf(wc, v.x, d.x); d.y = fmaf(wc, v.y, d.y);
        d.z = fmaf(wc, v.z, d.z); d.w = fmaf(wc, v.w, d.w);
    }
    int o = b * (HW_/4) + p4;
    const float inv = 1.0f / 256.0f;
    ((float4*)g_avg)[o] = make_float4(s.x*inv, s.y*inv, s.z*inv, s.w*inv);
    ((float4*)g_max)[o] = m;
    ((float4*)g_bm )[o] = make_float4(lrelu(d.x), lrelu(d.y), lrelu(d.z), lrelu(d.w));
}

// ---------------- k2: multi-scale convs -> F planes + Cm -----------------
__global__ void k2_convs(const float* __restrict__ w1,
                         const float* __restrict__ w3,
                         const float* __restrict__ w5,
                         const float* __restrict__ w7,
                         const float* __restrict__ w_fc) {
    const int b  = blockIdx.z;
    const int h0 = blockIdx.y * 32;
    const int w0 = blockIdx.x * 32;

    __shared__ float sA[38][39];
    __shared__ float sM[38][39];

    int tid = threadIdx.y * 32 + threadIdx.x;
    const float* avgb = g_avg + b * HW_;
    const float* maxb = g_max + b * HW_;

    for (int t = tid; t < 38 * 38; t += 1024) {
        int r = t / 38, c = t - r * 38;
        int hh = h0 + r - 3, ww = w0 + c - 3;
        bool in = (hh >= 0 && hh < H_ && ww >= 0 && ww < W_);
        sA[r][c] = in ? avgb[hh * W_ + ww] : 0.0f;
        sM[r][c] = in ? maxb[hh * W_ + ww] : 0.0f;
    }
    __syncthreads();

    int ty = threadIdx.y, tx = threadIdx.x;
    int cy = ty + 3, cx = tx + 3;

    float s1 = w1[0] * sA[cy][cx] + w1[1] * sM[cy][cx];

    float s3 = 0.0f;
#pragma unroll
    for (int kh = 0; kh < 3; kh++)
#pragma unroll
        for (int kw = 0; kw < 3; kw++) {
            s3 += w3[kh * 3 + kw]      * sA[cy + kh - 1][cx + kw - 1];
            s3 += w3[9 + kh * 3 + kw]  * sM[cy + kh - 1][cx + kw - 1];
        }

    float s5 = 0.0f;
#pragma unroll
    for (int kh = 0; kh < 5; kh++)
#pragma unroll
        for (int kw = 0; kw < 5; kw++) {
            s5 += w5[kh * 5 + kw]       * sA[cy + kh - 2][cx + kw - 2];
            s5 += w5[25 + kh * 5 + kw]  * sM[cy + kh - 2][cx + kw - 2];
        }

    float s7 = 0.0f;
#pragma unroll
    for (int kh = 0; kh < 7; kh++)
#pragma unroll
        for (int kw = 0; kw < 7; kw++) {
            s7 += w7[kh * 7 + kw]       * sA[cy + kh - 3][cx + kw - 3];
            s7 += w7[49 + kh * 7 + kw]  * sM[cy + kh - 3][cx + kw - 3];
        }

    s1 = lrelu(s1); s3 = lrelu(s3); s5 = lrelu(s5); s7 = lrelu(s7);

    int h = h0 + ty, w = w0 + tx;
    size_t base = (size_t)b * 4 * HW_ + h * W_ + w;
    g_F[base]           = s1;
    g_F[base + HW_]     = s3;
    g_F[base + 2 * HW_] = s5;
    g_F[base + 3 * HW_] = s7;

    g_Cm[b * HW_ + h * W_ + w] =
        lrelu(w_fc[0] * s1 + w_fc[1] * s3 + w_fc[2] * s5 + w_fc[3] * s7);
}

// ---------------- k3: attention scores + softmax (exact fp32) ------------
__global__ void k3_attn() {
    const int h = blockIdx.x;
    const int b = blockIdx.y;
    const int tid = threadIdx.x;

    __shared__ float sb2[W_];
    __shared__ float red[256];

    const float* bmrow = g_bm + b * HW_ + h * W_;
    if (tid < W_) sb2[tid] = bmrow[tid];
    __syncthreads();

    float acc = 0.0f;
    if (tid < H_) {
        const float* cm = g_Cm + b * HW_ + tid;
#pragma unroll 8
        for (int w = 0; w < W_; w++)
            acc = fmaf(sb2[w], cm[w * W_], acc);
    }

    red[tid] = (tid < H_) ? acc : -3.4e38f;
    __syncthreads();
    for (int s = 128; s > 0; s >>= 1) {
        if (tid < s) red[tid] = fmaxf(red[tid], red[tid + s]);
        __syncthreads();
    }
    float mx = red[0];
    __syncthreads();

    float e = (tid < H_) ? __expf(acc - mx) : 0.0f;
    red[tid] = e;
    __syncthreads();
    for (int s = 128; s > 0; s >>= 1) {
        if (tid < s) red[tid] += red[tid + s];
        __syncthreads();
    }
    if (tid < H_)
        g_S[((size_t)b * H_ + h) * H_ + tid] = e * (1.0f / red[0]);
}

// ---------------- k5: E_c = S_b @ D_c, TF32 MMA, S resident, K chunk 32 ---
#define SA_P 164           // S pitch: 164%32=4 -> conflict-free fragments
#define SB_P 168           // D pitch: 168%32=8 -> conflict-free fragments
#define K5_SMEM ((H_*SA_P + 2*32*SB_P)*4)
__global__ void __launch_bounds__(256)
k5_E(const float* __restrict__ w_fd) {
    extern __shared__ float sm5[];
    float* sA = sm5;                   // [160][SA_P] : full S tile
    float* sB = sm5 + H_ * SA_P;       // [2][32][SB_P]

    const int c = blockIdx.x;
    const int b = blockIdx.y;

    const float f0 = w_fd[c * 4 + 0];
    const float f1 = w_fd[c * 4 + 1];
    const float f2 = w_fd[c * 4 + 2];
    const float f3 = w_fd[c * 4 + 3];

    const float* Sb = g_S + (size_t)b * H_ * H_;
    const float* F0 = g_F + (size_t)b * 4 * HW_;
    const float* F1 = F0 + HW_;
    const float* F2 = F0 + 2 * HW_;
    const float* F3 = F0 + 3 * HW_;

    const int tid  = threadIdx.x;
    const int wid  = tid >> 5;
    const int lane = tid & 31;
    const int qr   = lane >> 2;
    const int qc   = lane & 3;
    const int mw0  = (wid & 1) * 80;
    const int nw0  = (wid >> 1) * 40;

    // stage full S via cp.async: 160 rows x 40 16B units
    for (int t = tid; t < H_ * 40; t += 256) {
        int row = t / 40, seg = t - row * 40;
        cp_async16(sA + row * SA_P + seg * 4, Sb + row * H_ + seg * 4);
    }
    cp_commit();

    // build first D chunk (k 0..31) into buffer 0
    {
        float* dst = sB;
#pragma unroll
        for (int j = 0; j < 10; j++) {
            int i2 = tid + j * 256;            // 2560 float2 per chunk
            int k  = i2 / 80, w2 = (i2 - k * 80) * 2;
            int row = k * W_ + w2;
            float2 a0 = *(const float2*)&F0[row];
            float2 a1 = *(const float2*)&F1[row];
            float2 a2 = *(const float2*)&F2[row];
            float2 a3 = *(const float2*)&F3[row];
            float2 r;
            r.x = lrelu(f0*a0.x + f1*a1.x + f2*a2.x + f3*a3.x);
            r.y = lrelu(f0*a0.y + f1*a1.y + f2*a2.y + f3*a3.y);
            *(float2*)&dst[k * SB_P + w2] = r;
        }
    }
    cp_wait<0>();
    __syncthreads();

    float acc[5][5][4];
#pragma unroll
    for (int i = 0; i < 5; i++)
#pragma unroll
        for (int j = 0; j < 5; j++)
#pragma unroll
            for (int q = 0; q < 4; q++) acc[i][j][q] = 0.0f;

    int buf = 0;
    for (int it = 0; it < 5; it++) {
        const int kc = it * 32;
        const float* bcur = sB + buf * 32 * SB_P;

#pragma unroll
        for (int kk = 0; kk < 32; kk += 8) {
            float Af[5][4];
#pragma unroll
            for (int mi = 0; mi < 5; mi++) {
                int m0 = mw0 + mi * 16;
                const float* ar = sA + kc + kk + qc;
                Af[mi][0] = ar[(m0 + qr)     * SA_P];
                Af[mi][1] = ar[(m0 + qr + 8) * SA_P];
                Af[mi][2] = ar[(m0 + qr)     * SA_P + 4];
                Af[mi][3] = ar[(m0 + qr + 8) * SA_P + 4];
            }
#pragma unroll
            for (int ni = 0; ni < 5; ni++) {
                int n0 = nw0 + ni * 8;
                float b0 = bcur[(kk + qc)     * SB_P + n0 + qr];
                float b1 = bcur[(kk + qc + 4) * SB_P + n0 + qr];
#pragma unroll
                for (int mi = 0; mi < 5; mi++)
                    mma_tf32(acc[mi][ni][0], acc[mi][ni][1],
                             acc[mi][ni][2], acc[mi][ni][3],
                             Af[mi][0], Af[mi][1], Af[mi][2], Af[mi][3],
                             b0, b1);
            }
        }

        if (it < 4) {                         // build next D chunk
            float* dst = sB + (buf ^ 1) * 32 * SB_P;
            const int kn = kc + 32;
#pragma unroll
            for (int j = 0; j < 10; j++) {
                int i2 = tid + j * 256;
                int k  = i2 / 80, w2 = (i2 - k * 80) * 2;
                int row = (kn + k) * W_ + w2;
                float2 a0 = *(const float2*)&F0[row];
                float2 a1 = *(const float2*)&F1[row];
                float2 a2 = *(const float2*)&F2[row];
                float2 a3 = *(const float2*)&F3[row];
                float2 r;
                r.x = lrelu(f0*a0.x + f1*a1.x + f2*a2.x + f3*a3.x);
                r.y = lrelu(f0*a0.y + f1*a1.y + f2*a2.y + f3*a3.y);
                *(float2*)&dst[k * SB_P + w2] = r;
            }
        }
        __syncthreads();
        buf ^= 1;
    }

    float* Eb = g_E + ((size_t)(b * C_ + c)) * HW_;
#pragma unroll
    for (int mi = 0; mi < 5; mi++) {
        int r0 = mw0 + mi * 16 + qr;
#pragma unroll
        for (int ni = 0; ni < 5; ni++) {
            int col = nw0 + ni * 8 + 2 * qc;
            *(float2*)&Eb[r0 * W_ + col]       = make_float2(acc[mi][ni][0], acc[mi][ni][1]);
            *(float2*)&Eb[(r0 + 8) * W_ + col] = make_float2(acc[mi][ni][2], acc[mi][ni][3]);
        }
    }
}

// ---------------- k6: out = W_e @ E + x, TF32 MMA, both streamed ----------
// tile 256(o) x 64(p); 8 warps 4x2; warp 64x32; K chunk 16; 3-stage ring.
#define WP6 20             // sW pitch [256][20]: bank(20*qr+qc) all distinct
#define EP6 72             // sE pitch [16][72]:  72%32=8 -> conflict-free
#define K6_STG ((256*WP6 + 16*EP6))
#define K6_SMEM (3*K6_STG*4)
__global__ void __launch_bounds__(256, 2)
k6_out(const float* __restrict__ w_e,
       const float* __restrict__ x,
       float* __restrict__ out) {
    extern __shared__ float sm6[];

    const int pb = blockIdx.x;     // 0..399
    const int b  = blockIdx.y;

    const int tid  = threadIdx.x;
    const int wid  = tid >> 5;
    const int lane = tid & 31;
    const int qr   = lane >> 2;
    const int qc   = lane & 3;
    const int mw0  = (wid & 3) * 64;     // warp M offset (o)
    const int nw0  = (wid >> 2) * 32;    // warp N offset (p)
    const int p0   = pb * 64;

    const float* Eb = g_E + (size_t)b * C_ * HW_ + p0;

    // stage chunk `ck` into ring slot `s`
    auto stage = [&](int s, int ck) {
        float* dW = sm6 + s * K6_STG;
        float* dE = dW + 256 * WP6;
        const int kc = ck * 16;
        // W: 256 rows x 4 16B units
        for (int t = tid; t < 1024; t += 256) {
            int row = t >> 2, seg = t & 3;
            cp_async16(dW + row * WP6 + seg * 4, w_e + row * C_ + kc + seg * 4);
        }
        // E: 16 rows x 16 16B units
        {
            int row = tid >> 4, seg = tid & 15;
            cp_async16(dE + row * EP6 + seg * 4,
                       Eb + (size_t)(kc + row) * HW_ + seg * 4);
        }
        cp_commit();
    };

    stage(0, 0);
    stage(1, 1);

    float acc[4][4][4];
#pragma unroll
    for (int i = 0; i < 4; i++)
#pragma unroll
        for (int j = 0; j < 4; j++)
#pragma unroll
            for (int q = 0; q < 4; q++) acc[i][j][q] = 0.0f;

    for (int it = 0; it < 16; it++) {
        if (it < 14) { stage((it + 2) % 3, it + 2); cp_wait<2>(); }
        else         { cp_wait<0>(); }
        __syncthreads();

        const float* sW = sm6 + (it % 3) * K6_STG;
        const float* sE = sW + 256 * WP6;

#pragma unroll
        for (int kk = 0; kk < 16; kk += 8) {
            float Af[4][4];
#pragma unroll
            for (int mi = 0; mi < 4; mi++) {
                int m0 = mw0 + mi * 16;
                const float* ar = sW + kk + qc;
                Af[mi][0] = ar[(m0 + qr)     * WP6];
                Af[mi][1] = ar[(m0 + qr + 8) * WP6];
                Af[mi][2] = ar[(m0 + qr)     * WP6 + 4];
                Af[mi][3] = ar[(m0 + qr + 8) * WP6 + 4];
            }
#pragma unroll
            for (int ni = 0; ni < 4; ni++) {
                int n0 = nw0 + ni * 8;
                float b0 = sE[(kk + qc)     * EP6 + n0 + qr];
                float b1 = sE[(kk + qc + 4) * EP6 + n0 + qr];
#pragma unroll
                for (int mi = 0; mi < 4; mi++)
                    mma_tf32(acc[mi][ni][0], acc[mi][ni][1],
                             acc[mi][ni][2], acc[mi][ni][3],
                             Af[mi][0], Af[mi][1], Af[mi][2], Af[mi][3],
                             b0, b1);
            }
        }
        __syncthreads();
    }

    const float* xb  = x   + (size_t)b * C_ * HW_ + p0;
    float*       obp = out + (size_t)b * C_ * HW_ + p0;
#pragma unroll
    for (int mi = 0; mi < 4; mi++) {
        int o = mw0 + mi * 16 + qr;
#pragma unroll
        for (int ni = 0; ni < 4; ni++) {
            int col = nw0 + ni * 8 + 2 * qc;
            {
                float2 xv = *(const float2*)&xb[(size_t)o * HW_ + col];
                *(float2*)&obp[(size_t)o * HW_ + col] =
                    make_float2(acc[mi][ni][0] + xv.x, acc[mi][ni][1] + xv.y);
            }
            {
                float2 xv = *(const float2*)&xb[(size_t)(o + 8) * HW_ + col];
                *(float2*)&obp[(size_t)(o + 8) * HW_ + col] =
                    make_float2(acc[mi][ni][2] + xv.x, acc[mi][ni][3] + xv.y);
            }
        }
    }
}

// ---------------- launch --------------------------------------------------
extern "C" void kernel_launch(void* const* d_in, const int* in_sizes, int n_in,
                              void* d_out, int out_size) {
    const float* x    = (const float*)d_in[0];
    const float* w1   = (const float*)d_in[1];
    const float* w3   = (const float*)d_in[2];
    const float* w5   = (const float*)d_in[3];
    const float* w7   = (const float*)d_in[4];
    const float* w_ab = (const float*)d_in[5];
    const float* w_fc = (const float*)d_in[6];
    const float* w_fd = (const float*)d_in[7];
    const float* w_e  = (const float*)d_in[8];
    float* out = (float*)d_out;

    cudaFuncSetAttribute(k5_E,   cudaFuncAttributeMaxDynamicSharedMemorySize, K5_SMEM);
    cudaFuncSetAttribute(k6_out, cudaFuncAttributeMaxDynamicSharedMemorySize, K6_SMEM);

    k1_reduce<<<dim3(HW_ / 1024, B_), 256>>>(x, w_ab);
    k2_convs <<<dim3(5, 5, B_), dim3(32, 32)>>>(w1, w3, w5, w7, w_fc);
    k3_attn  <<<dim3(H_, B_), 256>>>();
    k5_E     <<<dim3(C_, B_), 256, K5_SMEM>>>(w_fd);
    k6_out   <<<dim3(400, B_), 256, K6_SMEM>>>(w_e, x, out);
}

// round 14
// speedup vs baseline: 3.6024x; 1.0430x over previous
#include <cuda_runtime.h>
#include <cstdint>
#include <math.h>

#define B_  16
#define C_  256
#define H_  160
#define W_  160
#define HW_ (H_*W_)
#define NEG_SLOPE 0.001f

// ---------------- scratch -----------------------------------------------
__device__ float g_avg[B_*HW_];
__device__ float g_max[B_*HW_];
__device__ float g_bm [B_*HW_];
__device__ float g_F  [B_*4*HW_];
__device__ float g_Cm [B_*HW_];
__device__ float g_S  [B_*H_*H_];
__device__ float g_E  [(size_t)B_*C_*HW_];   // ~419 MB

__device__ __forceinline__ float lrelu(float v) {
    return v > 0.0f ? v : NEG_SLOPE * v;
}

__device__ __forceinline__ void cp_async16(void* smem_dst, const void* gmem_src) {
    unsigned int s = (unsigned int)__cvta_generic_to_shared(smem_dst);
    asm volatile("cp.async.ca.shared.global [%0], [%1], 16;\n" :: "r"(s), "l"(gmem_src));
}
__device__ __forceinline__ void cp_commit() {
    asm volatile("cp.async.commit_group;\n");
}
template<int N>
__device__ __forceinline__ void cp_wait() {
    asm volatile("cp.async.wait_group %0;\n" :: "n"(N));
}

// fp32 bits fed directly as tf32 operands (HW truncates low mantissa bits)
__device__ __forceinline__ void mma_tf32(float& c0, float& c1, float& c2, float& c3,
                                         float a0, float a1, float a2, float a3,
                                         float b0, float b1) {
    asm volatile(
        "mma.sync.aligned.m16n8k8.row.col.f32.tf32.tf32.f32 "
        "{%0,%1,%2,%3}, {%4,%5,%6,%7}, {%8,%9}, {%0,%1,%2,%3};"
        : "+f"(c0), "+f"(c1), "+f"(c2), "+f"(c3)
        : "r"(__float_as_uint(a0)), "r"(__float_as_uint(a1)),
          "r"(__float_as_uint(a2)), "r"(__float_as_uint(a3)),
          "r"(__float_as_uint(b0)), "r"(__float_as_uint(b1)));
}

// ---------------- k1: channel mean/max + w_ab dot, float4 ----------------
__global__ void k1_reduce(const float* __restrict__ x,
                          const float* __restrict__ w_ab) {
    __shared__ float sw[C_];
    int tid = threadIdx.x;
    sw[tid] = w_ab[tid];
    __syncthreads();

    int p4 = blockIdx.x * 256 + tid;
    int b  = blockIdx.y;
    const float4* xp = (const float4*)(x + (size_t)b * C_ * HW_) + p4;

    float4 s = make_float4(0,0,0,0);
    float4 m = make_float4(-3.4e38f,-3.4e38f,-3.4e38f,-3.4e38f);
    float4 d = make_float4(0,0,0,0);
#pragma unroll 4
    for (int c = 0; c < C_; c++) {
        float4 v = xp[(size_t)c * (HW_/4)];
        float wc = sw[c];
        s.x += v.x; s.y += v.y; s.z += v.z; s.w += v.w;
        m.x = fmaxf(m.x, v.x); m.y = fmaxf(m.y, v.y);
        m.z = fmaxf(m.z, v.z); m.w = fmaxf(m.w, v.w);
        d.x = fmaf(wc, v.x, d.x); d.y = fmaf(wc, v.y, d.y);
        d.z = fmaf(wc, v.z, d.z); d.w = fmaf(wc, v.w, d.w);
    }
    int o = b * (HW_/4) + p4;
    const float inv = 1.0f / 256.0f;
    ((float4*)g_avg)[o] = make_float4(s.x*inv, s.y*inv, s.z*inv, s.w*inv);
    ((float4*)g_max)[o] = m;
    ((float4*)g_bm )[o] = make_float4(lrelu(d.x), lrelu(d.y), lrelu(d.z), lrelu(d.w));
}

// ---------------- k2: multi-scale convs -> F planes + Cm -----------------
__global__ void k2_convs(const float* __restrict__ w1,
                         const float* __restrict__ w3,
                         const float* __restrict__ w5,
                         const float* __restrict__ w7,
                         const float* __restrict__ w_fc) {
    const int b  = blockIdx.z;
    const int h0 = blockIdx.y * 32;
    const int w0 = blockIdx.x * 32;

    __shared__ float sA[38][39];
    __shared__ float sM[38][39];

    int tid = threadIdx.y * 32 + threadIdx.x;
    const float* avgb = g_avg + b * HW_;
    const float* maxb = g_max + b * HW_;

    for (int t = tid; t < 38 * 38; t += 1024) {
        int r = t / 38, c = t - r * 38;
        int hh = h0 + r - 3, ww = w0 + c - 3;
        bool in = (hh >= 0 && hh < H_ && ww >= 0 && ww < W_);
        sA[r][c] = in ? avgb[hh * W_ + ww] : 0.0f;
        sM[r][c] = in ? maxb[hh * W_ + ww] : 0.0f;
    }
    __syncthreads();

    int ty = threadIdx.y, tx = threadIdx.x;
    int cy = ty + 3, cx = tx + 3;

    float s1 = w1[0] * sA[cy][cx] + w1[1] * sM[cy][cx];

    float s3 = 0.0f;
#pragma unroll
    for (int kh = 0; kh < 3; kh++)
#pragma unroll
        for (int kw = 0; kw < 3; kw++) {
            s3 += w3[kh * 3 + kw]      * sA[cy + kh - 1][cx + kw - 1];
            s3 += w3[9 + kh * 3 + kw]  * sM[cy + kh - 1][cx + kw - 1];
        }

    float s5 = 0.0f;
#pragma unroll
    for (int kh = 0; kh < 5; kh++)
#pragma unroll
        for (int kw = 0; kw < 5; kw++) {
            s5 += w5[kh * 5 + kw]       * sA[cy + kh - 2][cx + kw - 2];
            s5 += w5[25 + kh * 5 + kw]  * sM[cy + kh - 2][cx + kw - 2];
        }

    float s7 = 0.0f;
#pragma unroll
    for (int kh = 0; kh < 7; kh++)
#pragma unroll
        for (int kw = 0; kw < 7; kw++) {
            s7 += w7[kh * 7 + kw]       * sA[cy + kh - 3][cx + kw - 3];
            s7 += w7[49 + kh * 7 + kw]  * sM[cy + kh - 3][cx + kw - 3];
        }

    s1 = lrelu(s1); s3 = lrelu(s3); s5 = lrelu(s5); s7 = lrelu(s7);

    int h = h0 + ty, w = w0 + tx;
    size_t base = (size_t)b * 4 * HW_ + h * W_ + w;
    g_F[base]           = s1;
    g_F[base + HW_]     = s3;
    g_F[base + 2 * HW_] = s5;
    g_F[base + 3 * HW_] = s7;

    g_Cm[b * HW_ + h * W_ + w] =
        lrelu(w_fc[0] * s1 + w_fc[1] * s3 + w_fc[2] * s5 + w_fc[3] * s7);
}

// ---------------- k3: attention scores + softmax (exact fp32) ------------
__global__ void k3_attn() {
    const int h = blockIdx.x;
    const int b = blockIdx.y;
    const int tid = threadIdx.x;

    __shared__ float sb2[W_];
    __shared__ float red[256];

    const float* bmrow = g_bm + b * HW_ + h * W_;
    if (tid < W_) sb2[tid] = bmrow[tid];
    __syncthreads();

    float acc = 0.0f;
    if (tid < H_) {
        const float* cm = g_Cm + b * HW_ + tid;
#pragma unroll 8
        for (int w = 0; w < W_; w++)
            acc = fmaf(sb2[w], cm[w * W_], acc);
    }

    red[tid] = (tid < H_) ? acc : -3.4e38f;
    __syncthreads();
    for (int s = 128; s > 0; s >>= 1) {
        if (tid < s) red[tid] = fmaxf(red[tid], red[tid + s]);
        __syncthreads();
    }
    float mx = red[0];
    __syncthreads();

    float e = (tid < H_) ? __expf(acc - mx) : 0.0f;
    red[tid] = e;
    __syncthreads();
    for (int s = 128; s > 0; s >>= 1) {
        if (tid < s) red[tid] += red[tid + s];
        __syncthreads();
    }
    if (tid < H_)
        g_S[((size_t)b * H_ + h) * H_ + tid] = e * (1.0f / red[0]);
}

// ---------------- k5: E_c = S_b @ D_c, TF32 MMA, S resident --------------
// K chunk 16; next chunk's F data prefetched into REGISTERS during MMA.
#define SA_P 164           // S pitch: 164%32=4 -> conflict-free fragments
#define SB_P 168           // D pitch: 168%32=8 -> conflict-free fragments
#define K5_SMEM ((H_*SA_P + 2*16*SB_P)*4)
__global__ void __launch_bounds__(256)
k5_E(const float* __restrict__ w_fd) {
    extern __shared__ float sm5[];
    float* sA = sm5;                   // [160][SA_P] : full S tile
    float* sB = sm5 + H_ * SA_P;       // [2][16][SB_P]

    const int c = blockIdx.x;
    const int b = blockIdx.y;

    const float f0 = w_fd[c * 4 + 0];
    const float f1 = w_fd[c * 4 + 1];
    const float f2 = w_fd[c * 4 + 2];
    const float f3 = w_fd[c * 4 + 3];

    const float* Sb = g_S + (size_t)b * H_ * H_;
    const float* F0 = g_F + (size_t)b * 4 * HW_;
    const float* F1 = F0 + HW_;
    const float* F2 = F0 + 2 * HW_;
    const float* F3 = F0 + 3 * HW_;

    const int tid  = threadIdx.x;
    const int wid  = tid >> 5;
    const int lane = tid & 31;
    const int qr   = lane >> 2;
    const int qc   = lane & 3;
    const int mw0  = (wid & 1) * 80;
    const int nw0  = (wid >> 1) * 40;

    // per-thread element coords for D staging (5 float2 per chunk of 16 k)
    int dk[5], dw[5];
#pragma unroll
    for (int j = 0; j < 5; j++) {
        int i2 = tid + j * 256;            // 1280 float2 per chunk
        dk[j] = i2 / 80;
        dw[j] = (i2 - dk[j] * 80) * 2;
    }

    // stage full S via cp.async: 160 rows x 40 16B units
    for (int t = tid; t < H_ * 40; t += 256) {
        int row = t / 40, seg = t - row * 40;
        cp_async16(sA + row * SA_P + seg * 4, Sb + row * H_ + seg * 4);
    }
    cp_commit();

    // build first D chunk (k 0..15) into buffer 0
    {
#pragma unroll
        for (int j = 0; j < 5; j++) {
            int row = dk[j] * W_ + dw[j];
            float2 a0 = *(const float2*)&F0[row];
            float2 a1 = *(const float2*)&F1[row];
            float2 a2 = *(const float2*)&F2[row];
            float2 a3 = *(const float2*)&F3[row];
            float2 r;
            r.x = lrelu(f0*a0.x + f1*a1.x + f2*a2.x + f3*a3.x);
            r.y = lrelu(f0*a0.y + f1*a1.y + f2*a2.y + f3*a3.y);
            *(float2*)&sB[dk[j] * SB_P + dw[j]] = r;
        }
    }
    cp_wait<0>();
    __syncthreads();

    float acc[5][5][4];
#pragma unroll
    for (int i = 0; i < 5; i++)
#pragma unroll
        for (int j = 0; j < 5; j++)
#pragma unroll
            for (int q = 0; q < 4; q++) acc[i][j][q] = 0.0f;

    int buf = 0;
    for (int it = 0; it < 10; it++) {
        const int kc = it * 16;
        const float* bcur = sB + buf * 16 * SB_P;

        // prefetch next chunk's F data into registers (overlaps the MMAs)
        float2 p0[5], p1[5], p2[5], p3[5];
        if (it < 9) {
            const int kn = kc + 16;
#pragma unroll
            for (int j = 0; j < 5; j++) {
                int row = (kn + dk[j]) * W_ + dw[j];
                p0[j] = *(const float2*)&F0[row];
                p1[j] = *(const float2*)&F1[row];
                p2[j] = *(const float2*)&F2[row];
                p3[j] = *(const float2*)&F3[row];
            }
        }

#pragma unroll
        for (int kk = 0; kk < 16; kk += 8) {
            float Af[5][4];
#pragma unroll
            for (int mi = 0; mi < 5; mi++) {
                int m0 = mw0 + mi * 16;
                const float* ar = sA + kc + kk + qc;
                Af[mi][0] = ar[(m0 + qr)     * SA_P];
                Af[mi][1] = ar[(m0 + qr + 8) * SA_P];
                Af[mi][2] = ar[(m0 + qr)     * SA_P + 4];
                Af[mi][3] = ar[(m0 + qr + 8) * SA_P + 4];
            }
#pragma unroll
            for (int ni = 0; ni < 5; ni++) {
                int n0 = nw0 + ni * 8;
                float b0 = bcur[(kk + qc)     * SB_P + n0 + qr];
                float b1 = bcur[(kk + qc + 4) * SB_P + n0 + qr];
#pragma unroll
                for (int mi = 0; mi < 5; mi++)
                    mma_tf32(acc[mi][ni][0], acc[mi][ni][1],
                             acc[mi][ni][2], acc[mi][ni][3],
                             Af[mi][0], Af[mi][1], Af[mi][2], Af[mi][3],
                             b0, b1);
            }
        }

        if (it < 9) {                         // convert prefetched F -> D
            float* dst = sB + (buf ^ 1) * 16 * SB_P;
#pragma unroll
            for (int j = 0; j < 5; j++) {
                float2 r;
                r.x = lrelu(f0*p0[j].x + f1*p1[j].x + f2*p2[j].x + f3*p3[j].x);
                r.y = lrelu(f0*p0[j].y + f1*p1[j].y + f2*p2[j].y + f3*p3[j].y);
                *(float2*)&dst[dk[j] * SB_P + dw[j]] = r;
            }
        }
        __syncthreads();
        buf ^= 1;
    }

    float* Eb = g_E + ((size_t)(b * C_ + c)) * HW_;
#pragma unroll
    for (int mi = 0; mi < 5; mi++) {
        int r0 = mw0 + mi * 16 + qr;
#pragma unroll
        for (int ni = 0; ni < 5; ni++) {
            int col = nw0 + ni * 8 + 2 * qc;
            *(float2*)&Eb[r0 * W_ + col]       = make_float2(acc[mi][ni][0], acc[mi][ni][1]);
            *(float2*)&Eb[(r0 + 8) * W_ + col] = make_float2(acc[mi][ni][2], acc[mi][ni][3]);
        }
    }
}

// ---------------- k6: out = W_e @ E + x, TF32 MMA, both streamed ----------
// tile 256(o) x 64(p); 8 warps 4x2; warp 64x32; K chunk 16; 3-stage ring;
// ONE barrier per iteration.
#define WP6 20             // sW pitch [256][20]: bank(20*qr+qc) all distinct
#define EP6 72             // sE pitch [16][72]:  72%32=8 -> conflict-free
#define K6_STG ((256*WP6 + 16*EP6))
#define K6_SMEM (3*K6_STG*4)
__global__ void __launch_bounds__(256, 2)
k6_out(const float* __restrict__ w_e,
       const float* __restrict__ x,
       float* __restrict__ out) {
    extern __shared__ float sm6[];

    const int pb = blockIdx.x;     // 0..399
    const int b  = blockIdx.y;

    const int tid  = threadIdx.x;
    const int wid  = tid >> 5;
    const int lane = tid & 31;
    const int qr   = lane >> 2;
    const int qc   = lane & 3;
    const int mw0  = (wid & 3) * 64;     // warp M offset (o)
    const int nw0  = (wid >> 2) * 32;    // warp N offset (p)
    const int p0   = pb * 64;

    const float* Eb = g_E + (size_t)b * C_ * HW_ + p0;

    // stage chunk `ck` into ring slot `s`
    auto stage = [&](int s, int ck) {
        float* dW = sm6 + s * K6_STG;
        float* dE = dW + 256 * WP6;
        const int kc = ck * 16;
        // W: 256 rows x 4 16B units
        for (int t = tid; t < 1024; t += 256) {
            int row = t >> 2, seg = t & 3;
            cp_async16(dW + row * WP6 + seg * 4, w_e + row * C_ + kc + seg * 4);
        }
        // E: 16 rows x 16 16B units
        {
            int row = tid >> 4, seg = tid & 15;
            cp_async16(dE + row * EP6 + seg * 4,
                       Eb + (size_t)(kc + row) * HW_ + seg * 4);
        }
        cp_commit();
    };

    stage(0, 0);
    stage(1, 1);

    float acc[4][4][4];
#pragma unroll
    for (int i = 0; i < 4; i++)
#pragma unroll
        for (int j = 0; j < 4; j++)
#pragma unroll
            for (int q = 0; q < 4; q++) acc[i][j][q] = 0.0f;

    for (int it = 0; it < 16; it++) {
        if (it < 15) cp_wait<1>();   // chunk `it` landed; it+1 may be in flight
        else         cp_wait<0>();
        __syncthreads();             // data visible; prev compute on slot done
        if (it < 14) stage((it + 2) % 3, it + 2);

        const float* sW = sm6 + (it % 3) * K6_STG;
        const float* sE = sW + 256 * WP6;

#pragma unroll
        for (int kk = 0; kk < 16; kk += 8) {
            float Af[4][4];
#pragma unroll
            for (int mi = 0; mi < 4; mi++) {
                int m0 = mw0 + mi * 16;
                const float* ar = sW + kk + qc;
                Af[mi][0] = ar[(m0 + qr)     * WP6];
                Af[mi][1] = ar[(m0 + qr + 8) * WP6];
                Af[mi][2] = ar[(m0 + qr)     * WP6 + 4];
                Af[mi][3] = ar[(m0 + qr + 8) * WP6 + 4];
            }
#pragma unroll
            for (int ni = 0; ni < 4; ni++) {
                int n0 = nw0 + ni * 8;
                float b0 = sE[(kk + qc)     * EP6 + n0 + qr];
                float b1 = sE[(kk + qc + 4) * EP6 + n0 + qr];
#pragma unroll
                for (int mi = 0; mi < 4; mi++)
                    mma_tf32(acc[mi][ni][0], acc[mi][ni][1],
                             acc[mi][ni][2], acc[mi][ni][3],
                             Af[mi][0], Af[mi][1], Af[mi][2], Af[mi][3],
                             b0, b1);
            }
        }
    }

    const float* xb  = x   + (size_t)b * C_ * HW_ + p0;
    float*       obp = out + (size_t)b * C_ * HW_ + p0;
#pragma unroll
    for (int mi = 0; mi < 4; mi++) {
        int o = mw0 + mi * 16 + qr;
#pragma unroll
        for (int ni = 0; ni < 4; ni++) {
            int col = nw0 + ni * 8 + 2 * qc;
            {
                float2 xv = *(const float2*)&xb[(size_t)o * HW_ + col];
                *(float2*)&obp[(size_t)o * HW_ + col] =
                    make_float2(acc[mi][ni][0] + xv.x, acc[mi][ni][1] + xv.y);
            }
            {
                float2 xv = *(const float2*)&xb[(size_t)(o + 8) * HW_ + col];
                *(float2*)&obp[(size_t)(o + 8) * HW_ + col] =
                    make_float2(acc[mi][ni][2] + xv.x, acc[mi][ni][3] + xv.y);
            }
        }
    }
}

// ---------------- launch --------------------------------------------------
extern "C" void kernel_launch(void* const* d_in, const int* in_sizes, int n_in,
                              void* d_out, int out_size) {
    const float* x    = (const float*)d_in[0];
    const float* w1   = (const float*)d_in[1];
    const float* w3   = (const float*)d_in[2];
    const float* w5   = (const float*)d_in[3];
    const float* w7   = (const float*)d_in[4];
    const float* w_ab = (const float*)d_in[5];
    const float* w_fc = (const float*)d_in[6];
    const float* w_fd = (const float*)d_in[7];
    const float* w_e  = (const float*)d_in[8];
    float* out = (float*)d_out;

    cudaFuncSetAttribute(k5_E,   cudaFuncAttributeMaxDynamicSharedMemorySize, K5_SMEM);
    cudaFuncSetAttribute(k6_out, cudaFuncAttributeMaxDynamicSharedMemorySize, K6_SMEM);

    k1_reduce<<<dim3(HW_ / 1024, B_), 256>>>(x, w_ab);
    k2_convs <<<dim3(5, 5, B_), dim3(32, 32)>>>(w1, w3, w5, w7, w_fc);
    k3_attn  <<<dim3(H_, B_), 256>>>();
    k5_E     <<<dim3(C_, B_), 256, K5_SMEM>>>(w_fd);
    k6_out   <<<dim3(400, B_), 256, K6_SMEM>>>(w_e, x, out);
}